// round 2
// baseline (speedup 1.0000x reference)
#include <cuda_runtime.h>

#define DIM_HEAD 64
#define DIM_MID  32
#define DIM_TAIL 16
#define UD       64

// One row is handled by 64 threads (2 warps); thread owns output dim j.
// W_mid/W_tail columns for dim j live in registers, preloaded once per thread
// and amortized over a grid-stride row loop.
__global__ __launch_bounds__(256)
void mde_kernel(const int*   __restrict__ x,
                const int*   __restrict__ grp,
                const float* __restrict__ head,
                const float* __restrict__ mid,
                const float* __restrict__ tail,
                const float* __restrict__ Wm,
                const float* __restrict__ bm,
                const float* __restrict__ Wt,
                const float* __restrict__ bt,
                float*       __restrict__ out,
                int B)
{
    const int j    = threadIdx.x & 63;   // output dim 0..63
    const int slot = threadIdx.x >> 6;   // row slot within block 0..3
    const long long stride = (long long)gridDim.x * 4;

    // ---- preload weights into registers (L1/L2 hits, amortized) ----
    float wm[DIM_MID];
    float wt[DIM_TAIL];
#pragma unroll
    for (int k = 0; k < DIM_MID; k++)  wm[k] = __ldg(Wm + j * DIM_MID  + k);
#pragma unroll
    for (int k = 0; k < DIM_TAIL; k++) wt[k] = __ldg(Wt + j * DIM_TAIL + k);
    const float bmj = __ldg(bm + j);
    const float btj = __ldg(bt + j);

    for (long long row = (long long)blockIdx.x * 4 + slot; row < B; row += stride) {
        const int xi = __ldg(x   + row);
        const int gi = __ldg(grp + row);
        float r;

        if (gi == 0) {
            // pure gather: warp-coalesced 128B per warp, 256B per row
            r = __ldg(head + (long long)xi * DIM_HEAD + j);
        } else if (gi == 1) {
            // 32-float vector, broadcast float4 loads; FMA against register W
            const float4* mv = (const float4*)(mid + (long long)xi * DIM_MID);
            float a0 = bmj, a1 = 0.0f;
#pragma unroll
            for (int q = 0; q < DIM_MID / 4; q++) {
                const float4 v = __ldg(mv + q);
                a0 = fmaf(v.x, wm[4 * q + 0], a0);
                a1 = fmaf(v.y, wm[4 * q + 1], a1);
                a0 = fmaf(v.z, wm[4 * q + 2], a0);
                a1 = fmaf(v.w, wm[4 * q + 3], a1);
            }
            r = a0 + a1;
        } else if (gi == 2) {
            const float4* tv = (const float4*)(tail + (long long)xi * DIM_TAIL);
            float a0 = btj, a1 = 0.0f;
#pragma unroll
            for (int q = 0; q < DIM_TAIL / 4; q++) {
                const float4 v = __ldg(tv + q);
                a0 = fmaf(v.x, wt[4 * q + 0], a0);
                a1 = fmaf(v.y, wt[4 * q + 1], a1);
                a0 = fmaf(v.z, wt[4 * q + 2], a0);
                a1 = fmaf(v.w, wt[4 * q + 3], a1);
            }
            r = a0 + a1;
        } else {
            r = 0.0f;  // groups outside {0,1,2}: reference leaves zeros
        }

        // streaming store: don't let the 512MB output evict tables from L2
        __stcs(out + row * (long long)UD + j, r);
    }
}

extern "C" void kernel_launch(void* const* d_in, const int* in_sizes, int n_in,
                              void* d_out, int out_size)
{
    // metadata order: x, frequency_groups, head_table, mid_table, tail_table,
    //                 W_mid, b_mid, W_tail, b_tail
    const int*   x    = (const int*)  d_in[0];
    const int*   grp  = (const int*)  d_in[1];
    const float* head = (const float*)d_in[2];
    const float* mid  = (const float*)d_in[3];
    const float* tail = (const float*)d_in[4];
    const float* Wm   = (const float*)d_in[5];
    const float* bm   = (const float*)d_in[6];
    const float* Wt   = (const float*)d_in[7];
    const float* bt   = (const float*)d_in[8];
    float* out = (float*)d_out;

    const int B = in_sizes[0];

    // grid-stride: enough blocks to fill the chip several times over,
    // small enough that weight preload amortizes (~100+ rows per thread-group)
    const int threads = 256;
    const int blocks  = 4096;
    mde_kernel<<<blocks, threads>>>(x, grp, head, mid, tail, Wm, bm, Wt, bt, out, B);
}

// round 3
// speedup vs baseline: 1.0579x; 1.0579x over previous
#include <cuda_runtime.h>

#define DIM_HEAD 64
#define DIM_MID  32
#define DIM_TAIL 16
#define UD       64

// One row = 128 threads: thread = (j, half). j = output dim 0..63,
// half owns K-slice [half*16, half*16+16) of W_mid row j (8-wide for tail).
// W stays register-resident (26 regs) -> ~48 regs/thread -> 5 blocks/SM.
// Partial dots combined with one shfl_xor; even lanes store (contiguous 64B/warp).
__global__ __launch_bounds__(256)
void mde_kernel(const int*   __restrict__ x,
                const int*   __restrict__ grp,
                const float* __restrict__ head,
                const float* __restrict__ mid,
                const float* __restrict__ tail,
                const float* __restrict__ Wm,
                const float* __restrict__ bm,
                const float* __restrict__ Wt,
                const float* __restrict__ bt,
                float*       __restrict__ out,
                int B)
{
    const int t    = threadIdx.x;
    const int half = t & 1;          // K-slice owner
    const int j    = (t >> 1) & 63;  // output dim
    const int slot = t >> 7;         // row slot within block: 0..1
    const long long stride = (long long)gridDim.x * 2;

    // ---- register-resident W slices (amortized over the row loop) ----
    float wm[DIM_MID / 2];
    float wt[DIM_TAIL / 2];
#pragma unroll
    for (int k = 0; k < DIM_MID / 2; k++)
        wm[k] = __ldg(Wm + j * DIM_MID + half * (DIM_MID / 2) + k);
#pragma unroll
    for (int k = 0; k < DIM_TAIL / 2; k++)
        wt[k] = __ldg(Wt + j * DIM_TAIL + half * (DIM_TAIL / 2) + k);
    const float bmj = half ? 0.0f : __ldg(bm + j);  // bias added once (even lane)
    const float btj = half ? 0.0f : __ldg(bt + j);

    for (long long row = (long long)blockIdx.x * 2 + slot; row < B; row += stride) {
        const int xi = __ldg(x   + row);
        const int gi = __ldg(grp + row);
        float r;

        if (gi == 0) {
            // pure gather: even lane loads its float; warp = 16 contiguous floats (64B)
            r = half ? 0.0f : __ldg(head + (long long)xi * DIM_HEAD + j);
        } else if (gi == 1) {
            // 16-float K-slice, 4x float4 (2 distinct 16B addrs per warp instr)
            const float4* mv = (const float4*)(mid + (long long)xi * DIM_MID
                                               + half * (DIM_MID / 2));
            float a0 = bmj, a1 = 0.0f;
#pragma unroll
            for (int q = 0; q < 4; q++) {
                const float4 v = __ldg(mv + q);
                a0 = fmaf(v.x, wm[4 * q + 0], a0);
                a1 = fmaf(v.y, wm[4 * q + 1], a1);
                a0 = fmaf(v.z, wm[4 * q + 2], a0);
                a1 = fmaf(v.w, wm[4 * q + 3], a1);
            }
            r = a0 + a1;
        } else if (gi == 2) {
            const float4* tv = (const float4*)(tail + (long long)xi * DIM_TAIL
                                               + half * (DIM_TAIL / 2));
            float a0 = btj, a1 = 0.0f;
#pragma unroll
            for (int q = 0; q < 2; q++) {
                const float4 v = __ldg(tv + q);
                a0 = fmaf(v.x, wt[4 * q + 0], a0);
                a1 = fmaf(v.y, wt[4 * q + 1], a1);
                a0 = fmaf(v.z, wt[4 * q + 2], a0);
                a1 = fmaf(v.w, wt[4 * q + 3], a1);
            }
            r = a0 + a1;
        } else {
            r = 0.0f;  // groups outside {0,1,2} stay zero
        }

        // combine the two K-halves (converged here; head/else contribute 0 on odd lane)
        const float val = r + __shfl_xor_sync(0xffffffffu, r, 1);

        // even lanes store: 16 contiguous floats per warp (full 32B sectors),
        // streaming so the 512MB output doesn't evict tables from L2
        if (half == 0)
            __stcs(out + row * (long long)UD + j, val);
    }
}

extern "C" void kernel_launch(void* const* d_in, const int* in_sizes, int n_in,
                              void* d_out, int out_size)
{
    // metadata order: x, frequency_groups, head_table, mid_table, tail_table,
    //                 W_mid, b_mid, W_tail, b_tail
    const int*   x    = (const int*)  d_in[0];
    const int*   grp  = (const int*)  d_in[1];
    const float* head = (const float*)d_in[2];
    const float* mid  = (const float*)d_in[3];
    const float* tail = (const float*)d_in[4];
    const float* Wm   = (const float*)d_in[5];
    const float* bm   = (const float*)d_in[6];
    const float* Wt   = (const float*)d_in[7];
    const float* bt   = (const float*)d_in[8];
    float* out = (float*)d_out;

    const int B = in_sizes[0];

    const int threads = 256;   // 2 rows per block iteration
    const int blocks  = 8192;  // ~122 rows per block-slot, preload amortizes
    mde_kernel<<<blocks, threads>>>(x, grp, head, mid, tail, Wm, bm, Wt, bt, out, B);
}

// round 4
// speedup vs baseline: 1.8333x; 1.7329x over previous
#include <cuda_runtime.h>
#include <cstdint>

#define ROWS_PS 8     // rows per pipeline stage
#define STAGES  8     // pipeline depth
#define UD      64

// ---------- PTX helpers ----------
__device__ __forceinline__ uint32_t smem_u32(const void* p) {
    uint32_t a;
    asm("{ .reg .u64 t; cvta.to.shared.u64 t, %1; cvt.u32.u64 %0, t; }"
        : "=r"(a) : "l"(p));
    return a;
}
__device__ __forceinline__ void cp_async16(uint32_t dst, const void* src) {
    asm volatile("cp.async.cg.shared.global [%0], [%1], 16;" :: "r"(dst), "l"(src));
}
__device__ __forceinline__ void cp_commit() {
    asm volatile("cp.async.commit_group;");
}
template <int N>
__device__ __forceinline__ void cp_wait() {
    asm volatile("cp.async.wait_group %0;" :: "n"(N));
}
// packed fp32x2 FMA (FFMA2) — halves dot-product instruction count
__device__ __forceinline__ void ffma2(float2& d, float2 a, float2 b) {
    asm("fma.rn.f32x2 %0, %1, %2, %0;"
        : "+l"(reinterpret_cast<unsigned long long&>(d))
        : "l"(reinterpret_cast<const unsigned long long&>(a)),
          "l"(reinterpret_cast<const unsigned long long&>(b)));
}

// Thread map (consumer): half = t&1 owns K-slice, j = (t>>1)&63 output dim.
// Producer: warp w fills row-slot w of a stage; lanes 0..15 cp.async 16B each.
__global__ __launch_bounds__(256)
void mde_pipe(const int*   __restrict__ x,
              const int*   __restrict__ grp,
              const float* __restrict__ head,
              const float* __restrict__ mid,
              const float* __restrict__ tail,
              const float* __restrict__ Wm,
              const float* __restrict__ bm,
              const float* __restrict__ Wt,
              const float* __restrict__ bt,
              float*       __restrict__ out,
              int B)
{
    __shared__ __align__(256) float buf[STAGES][ROWS_PS][UD]; // 16 KB ring
    __shared__ int gbuf[STAGES][ROWS_PS];

    const int t    = threadIdx.x;
    const int wid  = t >> 5;
    const int lane = t & 31;
    const int half = t & 1;
    const int j    = (t >> 1) & 63;

    // ---- register-resident packed weight slices ----
    float2 wmp[8], wtp[4];
#pragma unroll
    for (int q = 0; q < 8; q++)
        wmp[q] = make_float2(__ldg(Wm + j * 32 + half * 16 + 2 * q),
                             __ldg(Wm + j * 32 + half * 16 + 2 * q + 1));
#pragma unroll
    for (int q = 0; q < 4; q++)
        wtp[q] = make_float2(__ldg(Wt + j * 16 + half * 8 + 2 * q),
                             __ldg(Wt + j * 16 + half * 8 + 2 * q + 1));
    const float bmj = half ? 0.f : __ldg(bm + j);
    const float btj = half ? 0.f : __ldg(bt + j);

    const int C = (B + ROWS_PS - 1) / ROWS_PS;  // total chunks
    const int G = gridDim.x;
    const int b0 = blockIdx.x;

    // ---------- producer: async-gather one chunk into a stage ----------
    auto produce = [&](int chunk, int stage) {
        const int row = chunk * ROWS_PS + wid;
        if (chunk < C && row < B) {
            const int xi = __ldg(x + row);
            const int g  = __ldg(grp + row);
            if (lane == 0) gbuf[stage][wid] = g;
            const float* src = head;  // dummy
            int bytes = 0;
            if (g == 0)      { src = head + (size_t)xi * 64; bytes = 256; }
            else if (g == 1) { src = mid  + (size_t)xi * 32; bytes = 128; }
            else if (g == 2) { src = tail + (size_t)xi * 16; bytes = 64;  }
            if (lane < 16 && lane * 16 < bytes)
                cp_async16(smem_u32(&buf[stage][wid][lane * 4]), src + lane * 4);
        } else {
            if (lane == 0) gbuf[stage][wid] = -1;
        }
        cp_commit();  // every thread, every call (empty groups keep counts aligned)
    };

    // ---------- consumer: compute 8 rows of a stage ----------
    auto consume = [&](int chunk, int stage) {
#pragma unroll
        for (int p = 0; p < ROWS_PS / 2; p++) {
            const int slot = 2 * p + (t >> 7);        // warp-uniform
            const int row  = chunk * ROWS_PS + slot;
            if (row >= B) continue;
            const int g = gbuf[stage][slot];
            const float* d = buf[stage][slot];
            float r;
            if (g == 0) {
                r = half ? 0.f : d[j];
            } else if (g == 1) {
                float2 acc = make_float2(bmj, 0.f);
                const float4* v = (const float4*)(d + half * 16);
#pragma unroll
                for (int q = 0; q < 4; q++) {
                    const float4 vv = v[q];
                    ffma2(acc, make_float2(vv.x, vv.y), wmp[2 * q]);
                    ffma2(acc, make_float2(vv.z, vv.w), wmp[2 * q + 1]);
                }
                r = acc.x + acc.y;
            } else if (g == 2) {
                float2 acc = make_float2(btj, 0.f);
                const float4* v = (const float4*)(d + half * 8);
#pragma unroll
                for (int q = 0; q < 2; q++) {
                    const float4 vv = v[q];
                    ffma2(acc, make_float2(vv.x, vv.y), wtp[2 * q]);
                    ffma2(acc, make_float2(vv.z, vv.w), wtp[2 * q + 1]);
                }
                r = acc.x + acc.y;
            } else {
                r = 0.f;  // groups outside {0,1,2} stay zero
            }
            // combine K-halves (lane pairs share j and row)
            const float val = r + __shfl_xor_sync(0xffffffffu, r, 1);
            if (half == 0)
                __stcs(out + (size_t)row * UD + j, val);  // 64B/warp, streaming
        }
    };

    // ---------- pipeline ----------
#pragma unroll
    for (int s = 0; s < STAGES; s++)
        produce(b0 + s * G, s);

    const int nch = (b0 < C) ? (C - b0 + G - 1) / G : 0;

    for (int k = 0; k < nch; k++) {
        cp_wait<STAGES - 1>();   // oldest stage's gathers have landed
        __syncthreads();
        const int stage = k & (STAGES - 1);
        consume(b0 + k * G, stage);
        __syncthreads();         // stage fully consumed before refill
        produce(b0 + (k + STAGES) * G, stage);
    }
}

extern "C" void kernel_launch(void* const* d_in, const int* in_sizes, int n_in,
                              void* d_out, int out_size)
{
    // metadata order: x, frequency_groups, head_table, mid_table, tail_table,
    //                 W_mid, b_mid, W_tail, b_tail
    const int*   x    = (const int*)  d_in[0];
    const int*   grp  = (const int*)  d_in[1];
    const float* head = (const float*)d_in[2];
    const float* mid  = (const float*)d_in[3];
    const float* tail = (const float*)d_in[4];
    const float* Wm   = (const float*)d_in[5];
    const float* bm   = (const float*)d_in[6];
    const float* Wt   = (const float*)d_in[7];
    const float* bt   = (const float*)d_in[8];
    float* out = (float*)d_out;

    const int B = in_sizes[0];

    const int threads = 256;
    const int blocks  = 2048;   // 250k chunks / 2048 ≈ 122 chunks/block
    mde_pipe<<<blocks, threads>>>(x, grp, head, mid, tail, Wm, bm, Wt, bt, out, B);
}

// round 5
// speedup vs baseline: 4.2654x; 2.3266x over previous
#include <cuda_runtime.h>
#include <cstdint>

#define CAP 2097152   // >= BATCH (2,000,000)

// ---------------- device scratch (static: no allocation allowed) ----------------
__device__ int2 g_list[3][CAP];   // (row, xi) per group
__device__ int  g_counts[3];

// ---------------- PTX helpers ----------------
__device__ __forceinline__ uint32_t smem_u32(const void* p) {
    uint32_t a;
    asm("{ .reg .u64 t; cvta.to.shared.u64 t, %1; cvt.u32.u64 %0, t; }"
        : "=r"(a) : "l"(p));
    return a;
}
__device__ __forceinline__ void cp_async16(uint32_t dst, const void* src) {
    asm volatile("cp.async.cg.shared.global [%0], [%1], 16;" :: "r"(dst), "l"(src));
}
__device__ __forceinline__ void cp_commit() {
    asm volatile("cp.async.commit_group;");
}
template <int N>
__device__ __forceinline__ void cp_wait() {
    asm volatile("cp.async.wait_group %0;" :: "n"(N));
}
__device__ __forceinline__ void ffma2(float2& d, float2 a, float2 b) {
    asm("fma.rn.f32x2 %0, %1, %2, %0;"
        : "+l"(reinterpret_cast<unsigned long long&>(d))
        : "l"(reinterpret_cast<const unsigned long long&>(a)),
          "l"(reinterpret_cast<const unsigned long long&>(b)));
}

// ---------------- kernel 0: reset counters (graph replays need this) ----------------
__global__ void reset_k() {
    if (threadIdx.x < 3) g_counts[threadIdx.x] = 0;
}

// ---------------- kernel 1: compact rows by group ----------------
__global__ __launch_bounds__(512)
void compact_k(const int* __restrict__ x, const int* __restrict__ grp, int B) {
    __shared__ int s_cnt[3], s_base[3];
    const int tid = threadIdx.x;
    for (long long base = (long long)blockIdx.x * 512; base < B;
         base += (long long)gridDim.x * 512) {
        if (tid < 3) s_cnt[tid] = 0;
        __syncthreads();
        const long long row = base + tid;
        int g = -1, xi = 0, pos = -1;
        if (row < B) {
            g  = __ldg(grp + row);
            xi = __ldg(x + row);
            if ((unsigned)g < 3u) pos = atomicAdd(&s_cnt[g], 1);
        }
        __syncthreads();
        if (tid < 3) s_base[tid] = atomicAdd(&g_counts[tid], s_cnt[tid]);
        __syncthreads();
        if (pos >= 0) g_list[g][s_base[g] + pos] = make_int2((int)row, xi);
        __syncthreads();
    }
}

// ---------------- kernel 2: head = pure gather-copy (256B/row) ----------------
__global__ __launch_bounds__(256)
void head_k(const float* __restrict__ head, float* __restrict__ out) {
    const int n      = g_counts[0];
    const int gt     = blockIdx.x * 256 + threadIdx.x;
    const int seg    = gt & 15;                 // 16 threads x float4 = one row
    const int stride = (gridDim.x * 256) >> 4;
    for (int i = gt >> 4; i < n; i += stride) {
        const int2  e = __ldg(&g_list[0][i]);   // broadcast within 16-thread group
        const float4 v = __ldg((const float4*)(head + (size_t)e.y * 64) + seg);
        __stcs((float4*)(out + (size_t)e.x * 64) + seg, v);
    }
}

// ---------------- kernel 3: mid GEMV (32 -> 64), cp.async staged, branch-free ----
#define MSTAGES 4
#define MROWS   32
__global__ __launch_bounds__(256)
void mid_k(const float* __restrict__ mid, const float* __restrict__ Wm,
           const float* __restrict__ bm, float* __restrict__ out) {
    __shared__ __align__(128) float vbuf[MSTAGES][MROWS][32];   // 16 KB
    __shared__ int rbuf[MSTAGES][MROWS];

    const int n = g_counts[1];
    const int t = threadIdx.x;
    const int j = t & 63;               // output dim; 4 row-slots per block iter

    float2 w[16];
#pragma unroll
    for (int q = 0; q < 16; q++)
        w[q] = make_float2(__ldg(Wm + j * 32 + 2 * q), __ldg(Wm + j * 32 + 2 * q + 1));
    const float bj = __ldg(bm + j);

    const int C = (n + MROWS - 1) / MROWS;
    const int G = gridDim.x, b0 = blockIdx.x;
    const int prl = t >> 3, pseg = t & 7;   // producer: 32 rows x 8 segs (16B)

    auto produce = [&](int chunk, int st) {
        const int i = chunk * MROWS + prl;
        if (chunk < C && i < n) {
            const int2 e = __ldg(&g_list[1][i]);
            if (pseg == 0) rbuf[st][prl] = e.x;
            cp_async16(smem_u32(&vbuf[st][prl][pseg * 4]),
                       mid + (size_t)e.y * 32 + pseg * 4);
        } else if (pseg == 0) {
            rbuf[st][prl] = -1;
        }
        cp_commit();
    };

    auto consume = [&](int st) {
        const int slot = t >> 6;
#pragma unroll
        for (int p = 0; p < MROWS / 4; p++) {
            const int rl  = p * 4 + slot;          // warp-uniform
            const int row = rbuf[st][rl];
            const float4* v4 = (const float4*)vbuf[st][rl];
            float2 a0 = make_float2(bj, 0.f), a1 = make_float2(0.f, 0.f);
#pragma unroll
            for (int q = 0; q < 8; q++) {
                const float4 vv = v4[q];            // LDS.128 broadcast
                ffma2(a0, make_float2(vv.x, vv.y), w[2 * q]);
                ffma2(a1, make_float2(vv.z, vv.w), w[2 * q + 1]);
            }
            if (row >= 0)
                __stcs(out + (size_t)row * 64 + j, a0.x + a0.y + a1.x + a1.y);
        }
    };

#pragma unroll
    for (int s = 0; s < MSTAGES; s++) produce(b0 + s * G, s);
    const int nch = (b0 < C) ? (C - b0 + G - 1) / G : 0;
    for (int k = 0; k < nch; k++) {
        cp_wait<MSTAGES - 1>();
        __syncthreads();
        const int st = k & (MSTAGES - 1);
        consume(st);
        __syncthreads();
        produce(b0 + (k + MSTAGES) * G, st);
    }
}

// ---------------- kernel 4: tail GEMV (16 -> 64), same structure ----------------
#define TSTAGES 4
#define TROWS   64
__global__ __launch_bounds__(256)
void tail_k(const float* __restrict__ tail, const float* __restrict__ Wt,
            const float* __restrict__ bt, float* __restrict__ out) {
    __shared__ __align__(128) float vbuf[TSTAGES][TROWS][16];   // 16 KB
    __shared__ int rbuf[TSTAGES][TROWS];

    const int n = g_counts[2];
    const int t = threadIdx.x;
    const int j = t & 63;

    float2 w[8];
#pragma unroll
    for (int q = 0; q < 8; q++)
        w[q] = make_float2(__ldg(Wt + j * 16 + 2 * q), __ldg(Wt + j * 16 + 2 * q + 1));
    const float bj = __ldg(bt + j);

    const int C = (n + TROWS - 1) / TROWS;
    const int G = gridDim.x, b0 = blockIdx.x;
    const int prl = t >> 2, pseg = t & 3;   // producer: 64 rows x 4 segs (16B)

    auto produce = [&](int chunk, int st) {
        const int i = chunk * TROWS + prl;
        if (chunk < C && i < n) {
            const int2 e = __ldg(&g_list[2][i]);
            if (pseg == 0) rbuf[st][prl] = e.x;
            cp_async16(smem_u32(&vbuf[st][prl][pseg * 4]),
                       tail + (size_t)e.y * 16 + pseg * 4);
        } else if (pseg == 0) {
            rbuf[st][prl] = -1;
        }
        cp_commit();
    };

    auto consume = [&](int st) {
        const int slot = t >> 6;
#pragma unroll
        for (int p = 0; p < TROWS / 4; p++) {
            const int rl  = p * 4 + slot;
            const int row = rbuf[st][rl];
            const float4* v4 = (const float4*)vbuf[st][rl];
            float2 a0 = make_float2(bj, 0.f), a1 = make_float2(0.f, 0.f);
#pragma unroll
            for (int q = 0; q < 4; q++) {
                const float4 vv = v4[q];
                ffma2(a0, make_float2(vv.x, vv.y), w[2 * q]);
                ffma2(a1, make_float2(vv.z, vv.w), w[2 * q + 1]);
            }
            if (row >= 0)
                __stcs(out + (size_t)row * 64 + j, a0.x + a0.y + a1.x + a1.y);
        }
    };

#pragma unroll
    for (int s = 0; s < TSTAGES; s++) produce(b0 + s * G, s);
    const int nch = (b0 < C) ? (C - b0 + G - 1) / G : 0;
    for (int k = 0; k < nch; k++) {
        cp_wait<TSTAGES - 1>();
        __syncthreads();
        const int st = k & (TSTAGES - 1);
        consume(st);
        __syncthreads();
        produce(b0 + (k + TSTAGES) * G, st);
    }
}

// ---------------- launcher ----------------
extern "C" void kernel_launch(void* const* d_in, const int* in_sizes, int n_in,
                              void* d_out, int out_size)
{
    // metadata order: x, frequency_groups, head_table, mid_table, tail_table,
    //                 W_mid, b_mid, W_tail, b_tail
    const int*   x    = (const int*)  d_in[0];
    const int*   grp  = (const int*)  d_in[1];
    const float* head = (const float*)d_in[2];
    const float* mid  = (const float*)d_in[3];
    const float* tail = (const float*)d_in[4];
    const float* Wm   = (const float*)d_in[5];
    const float* bm   = (const float*)d_in[6];
    const float* Wt   = (const float*)d_in[7];
    const float* bt   = (const float*)d_in[8];
    float* out = (float*)d_out;

    const int B = in_sizes[0];

    reset_k<<<1, 32>>>();
    compact_k<<<1024, 512>>>(x, grp, B);
    head_k<<<2048, 256>>>(head, out);
    mid_k <<<1024, 256>>>(mid,  Wm, bm, out);
    tail_k<<<1024, 256>>>(tail, Wt, bt, out);
}